// round 16
// baseline (speedup 1.0000x reference)
#include <cuda_runtime.h>
#include <math.h>

// ---------------------------------------------------------------------------
// Problem constants
// ---------------------------------------------------------------------------
#define B_   2
#define P_   4000
#define NP_  4096
#define D_   64
#define M_   512
#define HW_  214272
#define BITW (HW_ / 32)           // 6696

#define S0_   ((size_t)B_ * 128 * HW_)
#define S2_   ((size_t)B_ * 64 * HW_)
#define OFF1_ (S0_)
#define OFF2_ (2 * S0_)
#define OFF3_ (2 * S0_ + S2_)
#define OFF4_ (OFF3_ + (size_t)B_ * P_ * D_)

// Tiling (R2 lineage)
#define TILE_P 64
#define TILE_T 128
#define PITCH  68        // 272 B rows; conflict-free LDS.128, 16B aligned
#define NTHR   256
#define PTILES 63                       // ceil(4000/64)
#define NB_PT  (PTILES * B_)            // 126
#define NB_MEM (PTILES * B_)            // 126
#define NB_ATT (NB_PT + NB_MEM)         // 252
#define NB_F   296                      // fill blocks
#define NB_TOT (NB_ATT + NB_F)          // 548

#define PLANE4 (HW_ / 4)                // 53568 float4 per plane
#define QUART4 (PLANE4 / 4)             // 13392 float4 per chunk
#define NCHUNK (640 * 4)                // 2560 chunks total

// dynamic shared layout (bytes) -- attention role; fill role uses first 53568B
#define SM_PL   0                                   // 64*68*4      = 17408
#define SM_PT   17408                               // 2*128*68*4   = 69632
#define SM_TKV  87040                               // 64*8*4       =  2048
#define SM_TKI  89088                               // 64*8*4       =  2048
#define SMEM_BYTES 91136                            // 2 blocks/SM: 182KB <= 227KB

__device__ int      g_winner[B_ * HW_];
__device__ unsigned g_bitmap[B_ * BITW];

// ---------------------------------------------------------------------------
__device__ __forceinline__ void cp16(void* dst, const void* src) {
    unsigned a = (unsigned)__cvta_generic_to_shared(dst);
    asm volatile("cp.async.cg.shared.global [%0], [%1], 16;" :: "r"(a), "l"(src));
}
__device__ __forceinline__ void cp_commit() {
    asm volatile("cp.async.commit_group;" ::: "memory");
}
__device__ __forceinline__ void cp_wait_all() {
    asm volatile("cp.async.wait_group 0;" ::: "memory");
}
__device__ __forceinline__ void fma2(unsigned long long& acc,
                                     unsigned long long a, unsigned long long b) {
    asm volatile("fma.rn.f32x2 %0, %1, %2, %0;" : "+l"(acc) : "l"(a), "l"(b));
}
__device__ __forceinline__ float pair_sum(unsigned long long v) {
    return __uint_as_float((unsigned)v) + __uint_as_float((unsigned)(v >> 32));
}

// ---------------------------------------------------------------------------
// Attention block (R2 core) + fused winner scatter in the epilogue.
// scat: base of the output tensor whose UPPER 64 planes this branch owns
//       (memory branch -> out0 at offset 0; point branch -> out1 at OFF1_).
// ---------------------------------------------------------------------------
__device__ void attn_block(const float* __restrict__ pillars,
                           const float* __restrict__ vecs,
                           int vstride, int npts,
                           float* __restrict__ out_pos,
                           float* __restrict__ scat,
                           const int* __restrict__ idx,
                           int bid, char* smem)
{
    float* s_pl  = (float*)(smem + SM_PL);
    float* s_pt  = (float*)(smem + SM_PT);
    float* s_tkv = (float*)(smem + SM_TKV);
    int*   s_tki = (int*)(smem + SM_TKI);

    const int t  = threadIdx.x;
    const int tx = t & 31;
    const int wy = t >> 5;
    const int b  = bid / PTILES;
    const int p0 = (bid % PTILES) * TILE_P;
    const int pvalid = min(TILE_P, P_ - p0);
    const float* __restrict__ vb = vecs + (size_t)b * vstride;
    const float* __restrict__ pb = pillars + ((size_t)b * P_ + p0) * D_;
    const unsigned FULL = 0xffffffffu;

    s_tkv[t]       = -INFINITY;
    s_tkv[t + 256] = -INFINITY;

#pragma unroll
    for (int q = 0; q < 8; ++q) {
        int lin = t + q * NTHR;
        int r = lin >> 4, c = (lin & 15) << 2;
        cp16(s_pt + r * PITCH + c, vb + r * D_ + c);
    }
    cp_commit();

#pragma unroll
    for (int q = 0; q < 4; ++q) {
        int lin = t + q * NTHR;
        int r = lin >> 4, c = (lin & 15) << 2;
        float4 v = make_float4(0.f, 0.f, 0.f, 0.f);
        if (r < pvalid) v = *(const float4*)(pb + r * D_ + c);
        *(float4*)(s_pl + r * PITCH + c) = v;
    }
    __syncthreads();

    float vmin[8];
#pragma unroll
    for (int i = 0; i < 8; ++i) vmin[i] = -INFINITY;

    const int NT = npts / TILE_T;
    for (int tile = 0; tile < NT; ++tile) {
        float* buf = s_pt + (tile & 1) * (TILE_T * PITCH);
        cp_wait_all();
        __syncthreads();
        if (tile + 1 < NT) {
            float* nb = s_pt + ((tile + 1) & 1) * (TILE_T * PITCH);
            const float* src = vb + (size_t)(tile + 1) * TILE_T * D_;
#pragma unroll
            for (int q = 0; q < 8; ++q) {
                int lin = t + q * NTHR;
                int r = lin >> 4, c = (lin & 15) << 2;
                cp16(nb + r * PITCH + c, src + r * D_ + c);
            }
            cp_commit();
        }

        unsigned long long acc[8][4];
#pragma unroll
        for (int i = 0; i < 8; ++i)
#pragma unroll
            for (int j = 0; j < 4; ++j) acc[i][j] = 0ull;

#pragma unroll
        for (int dc = 0; dc < D_; dc += 4) {
            unsigned long long a0[8], a1[8], x0[4], x1[4];
#pragma unroll
            for (int i = 0; i < 8; ++i) {
                ulonglong2 v = *(const ulonglong2*)(s_pl + ((wy << 3) + i) * PITCH + dc);
                a0[i] = v.x; a1[i] = v.y;
            }
#pragma unroll
            for (int j = 0; j < 4; ++j) {
                ulonglong2 v = *(const ulonglong2*)(buf + (tx + 32 * j) * PITCH + dc);
                x0[j] = v.x; x1[j] = v.y;
            }
#pragma unroll
            for (int i = 0; i < 8; ++i)
#pragma unroll
                for (int j = 0; j < 4; ++j) {
                    fma2(acc[i][j], a0[i], x0[j]);
                    fma2(acc[i][j], a1[i], x1[j]);
                }
        }

        // ---- top-8 maintenance: one batched ballot per tile ----
        const int base = tile * TILE_T;
        bool anyhit = false;
#pragma unroll
        for (int i = 0; i < 8; ++i) {
            float thr = vmin[i];
#pragma unroll
            for (int j = 0; j < 4; ++j)
                anyhit |= (pair_sum(acc[i][j]) > thr);
        }
        if (__ballot_sync(FULL, anyhit)) {
#pragma unroll
            for (int i = 0; i < 8; ++i) {
                const int pr = (wy << 3) + i;
                float thr = vmin[i];
                float s[4];
#pragma unroll
                for (int j = 0; j < 4; ++j) s[j] = pair_sum(acc[i][j]);
                unsigned any = __ballot_sync(FULL,
                    (s[0] > thr) | (s[1] > thr) | (s[2] > thr) | (s[3] > thr));
                if (any) {
                    float* tv = s_tkv + pr * 8;
                    int*   ti = s_tki + pr * 8;
#pragma unroll
                    for (int j = 0; j < 4; ++j) {
                        unsigned m = __ballot_sync(FULL, s[j] > thr);
                        while (m) {
                            int ln = __ffs(m) - 1; m &= m - 1;
                            float v = __shfl_sync(FULL, s[j], ln);
                            if (v > thr) {
                                int slot = 0; float mn = tv[0];
#pragma unroll
                                for (int k = 1; k < 8; ++k) {
                                    float x = tv[k];
                                    if (x < mn) { mn = x; slot = k; }
                                }
                                tv[slot] = v;
                                ti[slot] = base + ln + 32 * j;
                                thr = tv[0];
#pragma unroll
                                for (int k = 1; k < 8; ++k) thr = fminf(thr, tv[k]);
                            }
                        }
                    }
                    vmin[i] = thr;
                }
            }
        }
    }

    __syncwarp();
#pragma unroll 1
    for (int i = 0; i < 8; ++i) {
        const int pr = (wy << 3) + i;
        if (pr >= pvalid) break;
        float vals[8]; int id[8];
#pragma unroll
        for (int k = 0; k < 8; ++k) { vals[k] = s_tkv[pr * 8 + k]; id[k] = s_tki[pr * 8 + k]; }
        float mx = vals[0];
#pragma unroll
        for (int k = 1; k < 8; ++k) mx = fmaxf(mx, vals[k]);
        float w[8], ssum = 0.f;
#pragma unroll
        for (int k = 0; k < 8; ++k) { w[k] = expf(vals[k] - mx); ssum += w[k]; }
        float inv = 1.f / ssum;
        float a0 = 0.f, a1 = 0.f;
#pragma unroll
        for (int k = 0; k < 8; ++k) {
            const float* vp = vb + (size_t)id[k] * D_;
            float wk = w[k] * inv;
            a0 += wk * vp[tx];
            a1 += wk * vp[tx + 32];
        }
        const int p = p0 + pr;
        float* op = out_pos + ((size_t)b * P_ + p) * D_;
        op[tx] = a0;
        op[tx + 32] = a1;

        // fused winner scatter: this branch owns the upper planes of `scat`
        const int col = idx[b * P_ + p];
        if (g_winner[b * HW_ + col] == p) {
            size_t g0 = (size_t)b * 128 * HW_ + (size_t)(64 + tx) * HW_ + col;
            scat[g0] = a0;
            scat[g0 + (size_t)32 * HW_] = a1;
        }
    }
}

// ---------------------------------------------------------------------------
// Fill role, chunk-structured (verified R13/R14). Static planes: winner
// values; upper planes: zeros skipping winner columns (epilogues own those).
// ---------------------------------------------------------------------------
__device__ void fill_role(int fid, const float* __restrict__ pillars,
                          const float* __restrict__ scale,
                          float* __restrict__ out, char* smem)
{
    unsigned* s_bm = (unsigned*)smem;
    const int t = threadIdx.x;
    for (int i = t; i < B_ * BITW; i += NTHR) s_bm[i] = g_bitmap[i];
    __syncthreads();

    const float4 z = make_float4(0.f, 0.f, 0.f, 0.f);

    for (int c = fid; c < NCHUNK; c += NB_F) {
        const int plane = c >> 2;
        const int q0 = (c & 3) * QUART4;
        float4* __restrict__ dst = (float4*)out + (size_t)plane * PLANE4;

        int b, ch;
        const float* src;
        bool stat;
        if (plane < 512) {
            int pl = plane & 255;
            b = pl >> 7; ch = pl & 127;
            stat = ch < 64; src = pillars;
        } else {
            int pl = plane - 512;
            b = pl >> 6; ch = pl & 63;
            stat = true; src = scale;
        }

        const unsigned* bm = s_bm + b * BITW;
        if (!stat) {
            for (int f = q0 + t; f < q0 + QUART4; f += NTHR) {
                unsigned bits = (bm[f >> 3] >> ((f & 7) * 4)) & 0xFu;
                if (!bits) {
                    __stcs(dst + f, z);
                } else {
                    float* d = (float*)(dst + f);
                    if (!(bits & 1u)) d[0] = 0.f;
                    if (!(bits & 2u)) d[1] = 0.f;
                    if (!(bits & 4u)) d[2] = 0.f;
                    if (!(bits & 8u)) d[3] = 0.f;
                }
            }
        } else {
            const int* win = g_winner + b * HW_;
            const float* sp = src + (size_t)b * P_ * D_ + ch;
            for (int f = q0 + t; f < q0 + QUART4; f += NTHR) {
                float4 v = z;
                unsigned bits = (bm[f >> 3] >> ((f & 7) * 4)) & 0xFu;
                if (bits) {
                    int col = f << 2;
                    if (bits & 1u) v.x = sp[(size_t)win[col]     * D_];
                    if (bits & 2u) v.y = sp[(size_t)win[col + 1] * D_];
                    if (bits & 4u) v.z = sp[(size_t)win[col + 2] * D_];
                    if (bits & 8u) v.w = sp[(size_t)win[col + 3] * D_];
                }
                __stcs(dst + f, v);
            }
        }
    }
}

// ---------------------------------------------------------------------------
// Fused kernel — ATTENTION-FIRST ordering: bids [0,252) attention (wave 1
// packs 2 attention blocks on most SMs -> 16 FMA warps/SM), [252,548) fill
// (backfills as attention drains; saturates DRAM in the tail).
// ---------------------------------------------------------------------------
__global__ void __launch_bounds__(NTHR, 2)
fused_kernel(const float* __restrict__ pillars,
             const float* __restrict__ scale,
             const float* __restrict__ points,
             const float* __restrict__ W,
             const int* __restrict__ idx,
             float* __restrict__ out)
{
    extern __shared__ char smem[];
    const int bid = blockIdx.x;
    if (bid < NB_ATT) {
        const int isMem = bid >= NB_PT;
        const int abid = isMem ? bid - NB_PT : bid;
        attn_block(pillars,
                   isMem ? W : points,
                   isMem ? 0 : NP_ * D_,
                   isMem ? M_ : NP_,
                   out + (isMem ? OFF4_ : OFF3_),
                   isMem ? out : out + OFF1_,     // mem -> out0 upper, point -> out1 upper
                   idx, abid, smem);
    } else {
        fill_role(bid - NB_ATT, pillars, scale, out, smem);
    }
}

// ---------------------------------------------------------------------------
__global__ void pre1_kernel() {
    int i = blockIdx.x * blockDim.x + threadIdx.x;
    int4* w4 = (int4*)g_winner;
    if (i < (B_ * HW_) / 4) w4[i] = make_int4(-1, -1, -1, -1);
    if (i < B_ * BITW) g_bitmap[i] = 0u;
}
__global__ void pre2_kernel(const int* __restrict__ idx) {
    int i = blockIdx.x * blockDim.x + threadIdx.x;
    if (i < B_ * P_) {
        int b = i / P_;
        int col = idx[i];
        atomicMax(&g_winner[b * HW_ + col], i - b * P_);
        atomicOr(&g_bitmap[b * BITW + (col >> 5)], 1u << (col & 31));
    }
}

// ---------------------------------------------------------------------------
extern "C" void kernel_launch(void* const* d_in, const int* in_sizes, int n_in,
                              void* d_out, int out_size) {
    (void)in_sizes; (void)n_in; (void)out_size;
    const float* pillars = (const float*)d_in[0];
    const float* scale   = (const float*)d_in[1];
    const float* points  = (const float*)d_in[2];
    const float* W       = (const float*)d_in[3];
    const int*   idx     = (const int*)d_in[4];
    float* out = (float*)d_out;

    cudaFuncSetAttribute(fused_kernel,
                         cudaFuncAttributeMaxDynamicSharedMemorySize, SMEM_BYTES);

    pre1_kernel<<<(B_ * HW_ / 4 + 255) / 256, 256>>>();
    pre2_kernel<<<(B_ * P_ + 255) / 256, 256>>>(idx);
    fused_kernel<<<NB_TOT, NTHR, SMEM_BYTES>>>(pillars, scale, points, W, idx, out);
}